// round 15
// baseline (speedup 1.0000x reference)
#include <cuda_runtime.h>
#include <cuda_pipeline.h>

// ---------------------------------------------------------------------------
// SNN ResNet forward, 8 timesteps, B=32. fp32 smem-tiled convs with cp.async
// double buffering, odd-stride weight smem (conflict-free), CO_PT output
// channels per thread (input-load reuse) on pre and large deep layers.
// Fused LIF / masks / residuals / 1x1-s2 shortcuts / avgpool; layer-0 hoisted.
// ---------------------------------------------------------------------------

#define B 32
#define TSTEPS 8

#define OFF_M0  0u
#define OFF_M1  2097152u
#define OFF_M2  4194304u
#define OFF_M3  6291456u
#define OFF_M4  6815744u
#define OFF_M5  7340032u
#define OFF_M6  7602176u
#define OFF_M7  7864320u
#define OFF_M8  7995392u
#define OFF_M9  8126464u
#define OFF_M10 8192000u
#define MEM_TOTAL 8257536u

__device__ float g_mem[MEM_TOTAL];
__device__ float g_A[2097152];
__device__ float g_B[2097152];
__device__ float g_C[2097152];
__device__ float g_D[2097152];   // precomputed conv(x, w_pre0)

__global__ void zero_kernel(float* __restrict__ p, int n) {
    int i = blockIdx.x * blockDim.x + threadIdx.x;
    if (i < n) p[i] = 0.0f;
}

// elementwise LIF for layer 0, float4-vectorized (delta precomputed)
__global__ __launch_bounds__(256)
void lif0_kernel(const float4* __restrict__ delta, float4* __restrict__ mem,
                 const float4* __restrict__ mask, float4* __restrict__ out,
                 const float* __restrict__ thr_a, const float* __restrict__ leak_a) {
    int i = blockIdx.x * blockDim.x + threadIdx.x;
    float thr = __ldg(thr_a), leak = __ldg(leak_a);
    float4 d = __ldg(delta + i);
    float4 mm = mem[i];
    float4 mk = __ldg(mask + i);
    float4 o, nm;
    { float m = fmaf(leak, mm.x, d.x); float s = (m / thr > 1.0f) ? 1.0f : 0.0f;
      nm.x = m - thr * s; o.x = s * mk.x; }
    { float m = fmaf(leak, mm.y, d.y); float s = (m / thr > 1.0f) ? 1.0f : 0.0f;
      nm.y = m - thr * s; o.y = s * mk.y; }
    { float m = fmaf(leak, mm.z, d.z); float s = (m / thr > 1.0f) ? 1.0f : 0.0f;
      nm.z = m - thr * s; o.z = s * mk.z; }
    { float m = fmaf(leak, mm.w, d.w); float s = (m / thr > 1.0f) ? 1.0f : 0.0f;
      nm.w = m - thr * s; o.w = s * mk.w; }
    mem[i] = nm;
    out[i] = o;
}

// ---------------------------------------------------------------------------
// Fused 3x3 conv (pad=1) + (residual | fused 1x1-s2 shortcut) + LIF + mask
// (+ optional fused 2x2 avgpool). Double-buffered cp.async chunk staging.
// Each thread computes CO_PT consecutive output channels (input-load reuse).
// mem == nullptr  =>  raw conv output (no LIF), used for hoisted layer 0.
// ---------------------------------------------------------------------------
template<int H, int CI, int CO, int STRIDE, int CIC, int TH, int TW,
         int CO_T, int B_T, int NT, int SC_CI, int POOL, int CO_PT>
__global__ __launch_bounds__(NT)
void conv_fused(const float* __restrict__ in, const float* __restrict__ wgt,
                const float* __restrict__ res, const float* __restrict__ mask,
                const float* __restrict__ sc_in, const float* __restrict__ sc_w,
                float* __restrict__ mem, float* __restrict__ out,
                const float* __restrict__ thr_a, const float* __restrict__ leak_a,
                int lidx) {
    constexpr int HO = H / STRIDE;
    constexpr int WO = HO;
    constexpr int TILESH = HO / TH;
    constexpr int TILESW = WO / TW;
    constexpr int TILES = TILESH * TILESW;
    constexpr int CO_G = CO_T / CO_PT;
    static_assert(TILES * CO_G * B_T == NT, "thread count mismatch");
    static_assert((TW * STRIDE) % 4 == 0 || TILESW == 1, "LDS.128 alignment");
    constexpr int RH = (TH - 1) * STRIDE + 3;
    constexpr int RW = (TW - 1) * STRIDE + 3;
    constexpr int NV4 = (RW + 3) / 4;
    constexpr int SWMIN = (H + 2 > NV4 * 4) ? (H + 2) : (NV4 * 4);
    constexpr int SW = ((SWMIN + 3) / 4) * 4;   // smem row stride (interior col 1)
    constexpr int HI2 = H + 2;
    constexpr int IN_CH = HI2 * SW;
    constexpr int IN_IMG = CIC * IN_CH;
    constexpr int IN_TOT = B_T * IN_IMG;
    constexpr int W_CO = CIC * 9;
    constexpr int W_STRIDE = W_CO + 1;          // ODD stride -> conflict-free
    constexpr int W_TOT = CO_T * W_STRIDE;
    constexpr int CHUNKS = CI / CIC;
    constexpr int THW = TH * TW;

    __shared__ alignas(16) float s_in[2][IN_TOT];
    __shared__ alignas(16) float s_w[2][W_TOT];

    const int tid = threadIdx.x;
    const int tile = tid % TILES;
    const int cs   = (tid / TILES) % CO_G;
    const int b_l  = tid / (TILES * CO_G);
    const int co_g = blockIdx.x % (CO / CO_T);
    const int b_g  = blockIdx.x / (CO / CO_T);
    const int b  = b_g * B_T + b_l;
    const int co = co_g * CO_T + cs * CO_PT;
    const int oh0 = (tile / TILESW) * TH;
    const int ow0 = (tile % TILESW) * TW;

    // zero both input buffers once: halo / padding stays zero for all chunks
    {
        const float4 z4 = make_float4(0.f, 0.f, 0.f, 0.f);
        for (int i = tid * 4; i < IN_TOT; i += NT * 4) {
            *reinterpret_cast<float4*>(&s_in[0][i]) = z4;
            *reinterpret_cast<float4*>(&s_in[1][i]) = z4;
        }
    }
    __syncthreads();

    auto stage = [&](int buf, int cc) {
        constexpr int NE = B_T * CIC * H * H;
        for (int e = tid; e < NE; e += NT) {
            const int wq = e % H;
            int r = e / H;
            const int h = r % H; r /= H;
            const int ci = r % CIC;
            const int bl = r / CIC;
            const float* src = in + (((size_t)(b_g * B_T + bl) * CI + cc * CIC + ci) * H + h) * H + wq;
            __pipeline_memcpy_async(&s_in[buf][bl * IN_IMG + ci * IN_CH + (h + 1) * SW + 1 + wq],
                                    src, 4);
        }
        for (int e = tid; e < CO_T * W_CO; e += NT) {
            const int rem = e % W_CO;
            const int col = e / W_CO;
            const float* src = wgt + ((size_t)(co_g * CO_T + col) * CI + cc * CIC) * 9 + rem;
            __pipeline_memcpy_async(&s_w[buf][col * W_STRIDE + rem], src, 4);
        }
    };

    float acc[CO_PT][THW];
#pragma unroll
    for (int p = 0; p < CO_PT; ++p)
#pragma unroll
        for (int i = 0; i < THW; ++i) acc[p][i] = 0.0f;

    stage(0, 0);
    __pipeline_commit();

    for (int cc = 0; cc < CHUNKS; ++cc) {
        const int cur = cc & 1;
        if (cc + 1 < CHUNKS) {
            stage(cur ^ 1, cc + 1);
            __pipeline_commit();
            __pipeline_wait_prior(1);
        } else {
            __pipeline_wait_prior(0);
        }
        __syncthreads();

        const float* sin_b = &s_in[cur][b_l * IN_IMG + (oh0 * STRIDE) * SW + ow0 * STRIDE];
        const float* sw_c  = &s_w[cur][(cs * CO_PT) * W_STRIDE];
        for (int ci = 0; ci < CIC; ++ci) {
            float w9[CO_PT][9];
#pragma unroll
            for (int p = 0; p < CO_PT; ++p)
#pragma unroll
                for (int k = 0; k < 9; ++k) w9[p][k] = sw_c[p * W_STRIDE + ci * 9 + k];
            const float* sp = sin_b + ci * IN_CH;
#pragma unroll
            for (int r = 0; r < RH; ++r) {
                float v[NV4 * 4];
#pragma unroll
                for (int q = 0; q < NV4; ++q)
                    *reinterpret_cast<float4*>(v + 4 * q) =
                        *reinterpret_cast<const float4*>(sp + r * SW + 4 * q);
#pragma unroll
                for (int kh = 0; kh < 3; ++kh) {
                    if (r - kh >= 0 && (r - kh) % STRIDE == 0 && (r - kh) / STRIDE < TH) {
                        const int ii = (r - kh) / STRIDE;
#pragma unroll
                        for (int kw = 0; kw < 3; ++kw)
#pragma unroll
                            for (int j = 0; j < TW; ++j)
#pragma unroll
                                for (int p = 0; p < CO_PT; ++p)
                                    acc[p][ii * TW + j] = fmaf(w9[p][kh * 3 + kw],
                                                               v[j * STRIDE + kw],
                                                               acc[p][ii * TW + j]);
                    }
                }
            }
        }
        __syncthreads();
    }

    // fused 1x1-s2 shortcut conv (input loads shared across CO_PT)
    float rsum[CO_PT][THW];
    if (SC_CI > 0) {
#pragma unroll
        for (int p = 0; p < CO_PT; ++p)
#pragma unroll
            for (int i = 0; i < THW; ++i) rsum[p][i] = 0.0f;
        for (int ci = 0; ci < SC_CI; ++ci) {
            float wv[CO_PT];
#pragma unroll
            for (int p = 0; p < CO_PT; ++p)
                wv[p] = __ldg(sc_w + (size_t)(co + p) * SC_CI + ci);
            const float* ip = sc_in + ((size_t)b * SC_CI + ci) * (4 * HO * WO);
#pragma unroll
            for (int i = 0; i < TH; ++i)
#pragma unroll
                for (int j = 0; j < TW; ++j) {
                    float iv = __ldg(ip + (2 * (oh0 + i)) * (2 * WO) + 2 * (ow0 + j));
#pragma unroll
                    for (int p = 0; p < CO_PT; ++p)
                        rsum[p][i * TW + j] = fmaf(wv[p], iv, rsum[p][i * TW + j]);
                }
        }
    }

    const float thr  = __ldg(thr_a + lidx);
    const float leak = __ldg(leak_a + lidx);

#pragma unroll
    for (int p = 0; p < CO_PT; ++p) {
        const int co_p = co + p;
        float s_tile[THW];
#pragma unroll
        for (int i = 0; i < TH; ++i) {
#pragma unroll
            for (int j = 0; j < TW; ++j) {
                size_t oi = (((size_t)b * CO + co_p) * HO + oh0 + i) * WO + ow0 + j;
                float d = acc[p][i * TW + j];
                if (SC_CI > 0) d += rsum[p][i * TW + j];
                else if (res) d += __ldg(res + oi);
                if (mem == nullptr) { out[oi] = d; continue; }
                float m = fmaf(leak, mem[oi], d);
                float mth = m / thr - 1.0f;
                float s = (mth > 0.0f) ? 1.0f : 0.0f;
                mem[oi] = m - thr * s;
                if (POOL) s_tile[i * TW + j] = s;
                else out[oi] = mask ? s * __ldg(mask + oi) : s;
            }
        }
        if (POOL && mem != nullptr) {
            constexpr int HOP = HO / 2, WOP = WO / 2;
#pragma unroll
            for (int i2 = 0; i2 < TH / 2; ++i2)
#pragma unroll
                for (int j2 = 0; j2 < TW / 2; ++j2) {
                    float sum = s_tile[(2 * i2) * TW + 2 * j2] +
                                s_tile[(2 * i2) * TW + 2 * j2 + 1] +
                                s_tile[(2 * i2 + 1) * TW + 2 * j2] +
                                s_tile[(2 * i2 + 1) * TW + 2 * j2 + 1];
                    out[(((size_t)b * CO + co_p) * HOP + (oh0 >> 1) + i2) * WOP +
                        (ow0 >> 1) + j2] = 0.25f * sum;
                }
        }
    }
}

// FC accumulate: out[b,j] += sum_k in[b,k] * wfc[j,k].  One warp per output.
__global__ __launch_bounds__(256)
void fc_acc(const float* __restrict__ in, const float* __restrict__ wfc,
            float* __restrict__ out) {
    int gw = (blockIdx.x * blockDim.x + threadIdx.x) >> 5;
    int lane = threadIdx.x & 31;
    if (gw >= B * 10) return;
    int b = gw / 10, j = gw % 10;
    const float* x = in + (size_t)b * 2048;
    const float* w = wfc + (size_t)j * 2048;
    float s = 0.f;
    for (int k = lane; k < 2048; k += 32) s = fmaf(x[k], w[k], s);
#pragma unroll
    for (int o = 16; o; o >>= 1) s += __shfl_down_sync(0xffffffffu, s, o);
    if (lane == 0) out[b * 10 + j] += s;
}

// -------------------------- host-side orchestration ------------------------

extern "C" void kernel_launch(void* const* d_in, const int* in_sizes, int n_in,
                              void* d_out, int out_size) {
    const float* x      = (const float*)d_in[0];
    const float* w_pre0 = (const float*)d_in[1];
    const float* w_pre1 = (const float*)d_in[2];
    const float* w_pre2 = (const float*)d_in[3];
    const float* w1a    = (const float*)d_in[4];
    const float* w1b    = (const float*)d_in[5];
    const float* w2a    = (const float*)d_in[6];
    const float* w2b    = (const float*)d_in[7];
    const float* w2i    = (const float*)d_in[8];
    const float* w3a    = (const float*)d_in[9];
    const float* w3b    = (const float*)d_in[10];
    const float* w3i    = (const float*)d_in[11];
    const float* w4a    = (const float*)d_in[12];
    const float* w4b    = (const float*)d_in[13];
    const float* w4i    = (const float*)d_in[14];
    const float* w_fc   = (const float*)d_in[15];
    const float* thr    = (const float*)d_in[16];
    const float* leak   = (const float*)d_in[17];
    const float* mask2  = (const float*)d_in[18];
    const float* mask5  = (const float*)d_in[19];
    const float* mask9  = (const float*)d_in[20];
    const float* mask11 = (const float*)d_in[21];
    const float* mask13 = (const float*)d_in[22];
    const float* mask15 = (const float*)d_in[23];

    float *pm, *pA, *pB, *pC, *pD;
    cudaGetSymbolAddress((void**)&pm, g_mem);
    cudaGetSymbolAddress((void**)&pA, g_A);
    cudaGetSymbolAddress((void**)&pB, g_B);
    cudaGetSymbolAddress((void**)&pC, g_C);
    cudaGetSymbolAddress((void**)&pD, g_D);

    float* m0  = pm + OFF_M0;
    float* m1  = pm + OFF_M1;
    float* m2  = pm + OFF_M2;
    float* m3  = pm + OFF_M3;
    float* m4  = pm + OFF_M4;
    float* m5  = pm + OFF_M5;
    float* m6  = pm + OFF_M6;
    float* m7  = pm + OFF_M7;
    float* m8  = pm + OFF_M8;
    float* m9  = pm + OFF_M9;
    float* m10 = pm + OFF_M10;

    zero_kernel<<<(MEM_TOTAL + 255) / 256, 256>>>(pm, (int)MEM_TOTAL);
    zero_kernel<<<2, 256>>>((float*)d_out, out_size);

    // hoisted: delta0 = conv(x, w_pre0), constant across timesteps
    conv_fused<32, 3, 64, 1, 3, 4, 4, 4, 1, 256, 0, 0, 1><<<512, 256>>>(
        x, w_pre0, nullptr, nullptr, nullptr, nullptr, nullptr, pD, thr, leak, 0);

    for (int t = 0; t < TSTEPS; ++t) {
        // layer 0: elementwise LIF on precomputed delta (float4)
        lif0_kernel<<<2048, 256>>>((const float4*)pD, (float4*)m0,
                                   (const float4*)mask2, (float4*)pA, thr + 0, leak + 0);

        // pre-process convs (32x32, 64ch), CO_PT=2; pre2 fuses the avgpool
        conv_fused<32, 64, 64, 1, 4, 4, 4, 8, 1, 256, 0, 0, 2><<<256, 256>>>(
            pA, w_pre1, nullptr, mask5, nullptr, nullptr, m1, pB, thr, leak, 1);
        conv_fused<32, 64, 64, 1, 4, 4, 4, 8, 1, 256, 0, 1, 2><<<256, 256>>>(
            pB, w_pre2, nullptr, nullptr, nullptr, nullptr, m2, pC, thr, leak, 2);

        // layer1 (identity shortcut), 16x16x64: CO_PT=2, same grid
        conv_fused<16, 64, 64, 1, 8, 4, 4, 16, 1, 128, 0, 0, 2><<<128, 128>>>(
            pC, w1a, nullptr, mask9, nullptr, nullptr, m3, pA, thr, leak, 3);
        conv_fused<16, 64, 64, 1, 8, 4, 4, 16, 1, 128, 0, 0, 2><<<128, 128>>>(
            pA, w1b, pC, nullptr, nullptr, nullptr, m4, pB, thr, leak, 4);

        // layer2: 16x16x64 -> 8x8x128 (fused 1x1-s2 shortcut in conv-b)
        conv_fused<16, 64, 128, 2, 4, 2, 4, 16, 2, 128, 0, 0, 2><<<128, 128>>>(
            pB, w2a, nullptr, mask11, nullptr, nullptr, m5, pC, thr, leak, 5);
        conv_fused<8, 128, 128, 1, 8, 4, 4, 16, 2, 128, 64, 0, 1><<<128, 128>>>(
            pC, w2b, nullptr, nullptr, pB, w2i, m6, pA, thr, leak, 6);

        // layer3: 8x8x128 -> 4x4x256
        conv_fused<8, 128, 256, 2, 8, 2, 2, 16, 2, 128, 0, 0, 1><<<256, 128>>>(
            pA, w3a, nullptr, mask13, nullptr, nullptr, m7, pB, thr, leak, 7);
        conv_fused<4, 256, 256, 1, 8, 2, 4, 32, 2, 128, 128, 0, 1><<<128, 128>>>(
            pB, w3b, nullptr, nullptr, pA, w3i, m8, pC, thr, leak, 8);

        // layer4: 4x4x256 -> 2x2x512
        conv_fused<4, 256, 512, 2, 8, 2, 2, 32, 4, 128, 0, 0, 1><<<128, 128>>>(
            pC, w4a, nullptr, mask15, nullptr, nullptr, m9, pB, thr, leak, 9);
        conv_fused<2, 512, 512, 1, 16, 2, 2, 32, 4, 128, 256, 0, 1><<<128, 128>>>(
            pB, w4b, nullptr, nullptr, pC, w4i, m10, pA, thr, leak, 10);

        // classifier accumulation
        fc_acc<<<40, 256>>>(pA, w_fc, (float*)d_out);
    }
}

// round 16
// speedup vs baseline: 1.0089x; 1.0089x over previous
#include <cuda_runtime.h>
#include <cuda_pipeline.h>

// ---------------------------------------------------------------------------
// SNN ResNet forward, 8 timesteps, B=32. fp32 smem-tiled convs with cp.async
// double buffering, odd-stride weight smem (conflict-free), CO_PT output
// channels per thread (input-load reuse) on pre convs and layer1 (warp count
// preserved via finer TH). Fused LIF / masks / residuals / 1x1-s2 shortcuts /
// avgpool; layer-0 conv hoisted out of the time loop.
// ---------------------------------------------------------------------------

#define B 32
#define TSTEPS 8

#define OFF_M0  0u
#define OFF_M1  2097152u
#define OFF_M2  4194304u
#define OFF_M3  6291456u
#define OFF_M4  6815744u
#define OFF_M5  7340032u
#define OFF_M6  7602176u
#define OFF_M7  7864320u
#define OFF_M8  7995392u
#define OFF_M9  8126464u
#define OFF_M10 8192000u
#define MEM_TOTAL 8257536u

__device__ float g_mem[MEM_TOTAL];
__device__ float g_A[2097152];
__device__ float g_B[2097152];
__device__ float g_C[2097152];
__device__ float g_D[2097152];   // precomputed conv(x, w_pre0)

__global__ void zero_kernel(float* __restrict__ p, int n) {
    int i = blockIdx.x * blockDim.x + threadIdx.x;
    if (i < n) p[i] = 0.0f;
}

// elementwise LIF for layer 0, float4-vectorized (delta precomputed)
__global__ __launch_bounds__(256)
void lif0_kernel(const float4* __restrict__ delta, float4* __restrict__ mem,
                 const float4* __restrict__ mask, float4* __restrict__ out,
                 const float* __restrict__ thr_a, const float* __restrict__ leak_a) {
    int i = blockIdx.x * blockDim.x + threadIdx.x;
    float thr = __ldg(thr_a), leak = __ldg(leak_a);
    float4 d = __ldg(delta + i);
    float4 mm = mem[i];
    float4 mk = __ldg(mask + i);
    float4 o, nm;
    { float m = fmaf(leak, mm.x, d.x); float s = (m / thr > 1.0f) ? 1.0f : 0.0f;
      nm.x = m - thr * s; o.x = s * mk.x; }
    { float m = fmaf(leak, mm.y, d.y); float s = (m / thr > 1.0f) ? 1.0f : 0.0f;
      nm.y = m - thr * s; o.y = s * mk.y; }
    { float m = fmaf(leak, mm.z, d.z); float s = (m / thr > 1.0f) ? 1.0f : 0.0f;
      nm.z = m - thr * s; o.z = s * mk.z; }
    { float m = fmaf(leak, mm.w, d.w); float s = (m / thr > 1.0f) ? 1.0f : 0.0f;
      nm.w = m - thr * s; o.w = s * mk.w; }
    mem[i] = nm;
    out[i] = o;
}

// ---------------------------------------------------------------------------
// Fused 3x3 conv (pad=1) + (residual | fused 1x1-s2 shortcut) + LIF + mask
// (+ optional fused 2x2 avgpool). Double-buffered cp.async chunk staging.
// Each thread computes CO_PT consecutive output channels (input-load reuse).
// mem == nullptr  =>  raw conv output (no LIF), used for hoisted layer 0.
// ---------------------------------------------------------------------------
template<int H, int CI, int CO, int STRIDE, int CIC, int TH, int TW,
         int CO_T, int B_T, int NT, int SC_CI, int POOL, int CO_PT>
__global__ __launch_bounds__(NT)
void conv_fused(const float* __restrict__ in, const float* __restrict__ wgt,
                const float* __restrict__ res, const float* __restrict__ mask,
                const float* __restrict__ sc_in, const float* __restrict__ sc_w,
                float* __restrict__ mem, float* __restrict__ out,
                const float* __restrict__ thr_a, const float* __restrict__ leak_a,
                int lidx) {
    constexpr int HO = H / STRIDE;
    constexpr int WO = HO;
    constexpr int TILESH = HO / TH;
    constexpr int TILESW = WO / TW;
    constexpr int TILES = TILESH * TILESW;
    constexpr int CO_G = CO_T / CO_PT;
    static_assert(TILES * CO_G * B_T == NT, "thread count mismatch");
    static_assert((TW * STRIDE) % 4 == 0 || TILESW == 1, "LDS.128 alignment");
    constexpr int RH = (TH - 1) * STRIDE + 3;
    constexpr int RW = (TW - 1) * STRIDE + 3;
    constexpr int NV4 = (RW + 3) / 4;
    constexpr int SWMIN = (H + 2 > NV4 * 4) ? (H + 2) : (NV4 * 4);
    constexpr int SW = ((SWMIN + 3) / 4) * 4;   // smem row stride (interior col 1)
    constexpr int HI2 = H + 2;
    constexpr int IN_CH = HI2 * SW;
    constexpr int IN_IMG = CIC * IN_CH;
    constexpr int IN_TOT = B_T * IN_IMG;
    constexpr int W_CO = CIC * 9;
    constexpr int W_STRIDE = W_CO + 1;          // ODD stride -> conflict-free
    constexpr int W_TOT = CO_T * W_STRIDE;
    constexpr int CHUNKS = CI / CIC;
    constexpr int THW = TH * TW;

    __shared__ alignas(16) float s_in[2][IN_TOT];
    __shared__ alignas(16) float s_w[2][W_TOT];

    const int tid = threadIdx.x;
    const int tile = tid % TILES;
    const int cs   = (tid / TILES) % CO_G;
    const int b_l  = tid / (TILES * CO_G);
    const int co_g = blockIdx.x % (CO / CO_T);
    const int b_g  = blockIdx.x / (CO / CO_T);
    const int b  = b_g * B_T + b_l;
    const int co = co_g * CO_T + cs * CO_PT;
    const int oh0 = (tile / TILESW) * TH;
    const int ow0 = (tile % TILESW) * TW;

    // zero both input buffers once: halo / padding stays zero for all chunks
    {
        const float4 z4 = make_float4(0.f, 0.f, 0.f, 0.f);
        for (int i = tid * 4; i < IN_TOT; i += NT * 4) {
            *reinterpret_cast<float4*>(&s_in[0][i]) = z4;
            *reinterpret_cast<float4*>(&s_in[1][i]) = z4;
        }
    }
    __syncthreads();

    auto stage = [&](int buf, int cc) {
        constexpr int NE = B_T * CIC * H * H;
        for (int e = tid; e < NE; e += NT) {
            const int wq = e % H;
            int r = e / H;
            const int h = r % H; r /= H;
            const int ci = r % CIC;
            const int bl = r / CIC;
            const float* src = in + (((size_t)(b_g * B_T + bl) * CI + cc * CIC + ci) * H + h) * H + wq;
            __pipeline_memcpy_async(&s_in[buf][bl * IN_IMG + ci * IN_CH + (h + 1) * SW + 1 + wq],
                                    src, 4);
        }
        for (int e = tid; e < CO_T * W_CO; e += NT) {
            const int rem = e % W_CO;
            const int col = e / W_CO;
            const float* src = wgt + ((size_t)(co_g * CO_T + col) * CI + cc * CIC) * 9 + rem;
            __pipeline_memcpy_async(&s_w[buf][col * W_STRIDE + rem], src, 4);
        }
    };

    float acc[CO_PT][THW];
#pragma unroll
    for (int p = 0; p < CO_PT; ++p)
#pragma unroll
        for (int i = 0; i < THW; ++i) acc[p][i] = 0.0f;

    stage(0, 0);
    __pipeline_commit();

    for (int cc = 0; cc < CHUNKS; ++cc) {
        const int cur = cc & 1;
        if (cc + 1 < CHUNKS) {
            stage(cur ^ 1, cc + 1);
            __pipeline_commit();
            __pipeline_wait_prior(1);
        } else {
            __pipeline_wait_prior(0);
        }
        __syncthreads();

        const float* sin_b = &s_in[cur][b_l * IN_IMG + (oh0 * STRIDE) * SW + ow0 * STRIDE];
        const float* sw_c  = &s_w[cur][(cs * CO_PT) * W_STRIDE];
        for (int ci = 0; ci < CIC; ++ci) {
            float w9[CO_PT][9];
#pragma unroll
            for (int p = 0; p < CO_PT; ++p)
#pragma unroll
                for (int k = 0; k < 9; ++k) w9[p][k] = sw_c[p * W_STRIDE + ci * 9 + k];
            const float* sp = sin_b + ci * IN_CH;
#pragma unroll
            for (int r = 0; r < RH; ++r) {
                float v[NV4 * 4];
#pragma unroll
                for (int q = 0; q < NV4; ++q)
                    *reinterpret_cast<float4*>(v + 4 * q) =
                        *reinterpret_cast<const float4*>(sp + r * SW + 4 * q);
#pragma unroll
                for (int kh = 0; kh < 3; ++kh) {
                    if (r - kh >= 0 && (r - kh) % STRIDE == 0 && (r - kh) / STRIDE < TH) {
                        const int ii = (r - kh) / STRIDE;
#pragma unroll
                        for (int kw = 0; kw < 3; ++kw)
#pragma unroll
                            for (int j = 0; j < TW; ++j)
#pragma unroll
                                for (int p = 0; p < CO_PT; ++p)
                                    acc[p][ii * TW + j] = fmaf(w9[p][kh * 3 + kw],
                                                               v[j * STRIDE + kw],
                                                               acc[p][ii * TW + j]);
                    }
                }
            }
        }
        __syncthreads();
    }

    // fused 1x1-s2 shortcut conv (input loads shared across CO_PT)
    float rsum[CO_PT][THW];
    if (SC_CI > 0) {
#pragma unroll
        for (int p = 0; p < CO_PT; ++p)
#pragma unroll
            for (int i = 0; i < THW; ++i) rsum[p][i] = 0.0f;
        for (int ci = 0; ci < SC_CI; ++ci) {
            float wv[CO_PT];
#pragma unroll
            for (int p = 0; p < CO_PT; ++p)
                wv[p] = __ldg(sc_w + (size_t)(co + p) * SC_CI + ci);
            const float* ip = sc_in + ((size_t)b * SC_CI + ci) * (4 * HO * WO);
#pragma unroll
            for (int i = 0; i < TH; ++i)
#pragma unroll
                for (int j = 0; j < TW; ++j) {
                    float iv = __ldg(ip + (2 * (oh0 + i)) * (2 * WO) + 2 * (ow0 + j));
#pragma unroll
                    for (int p = 0; p < CO_PT; ++p)
                        rsum[p][i * TW + j] = fmaf(wv[p], iv, rsum[p][i * TW + j]);
                }
        }
    }

    const float thr  = __ldg(thr_a + lidx);
    const float leak = __ldg(leak_a + lidx);

#pragma unroll
    for (int p = 0; p < CO_PT; ++p) {
        const int co_p = co + p;
        float s_tile[THW];
#pragma unroll
        for (int i = 0; i < TH; ++i) {
#pragma unroll
            for (int j = 0; j < TW; ++j) {
                size_t oi = (((size_t)b * CO + co_p) * HO + oh0 + i) * WO + ow0 + j;
                float d = acc[p][i * TW + j];
                if (SC_CI > 0) d += rsum[p][i * TW + j];
                else if (res) d += __ldg(res + oi);
                if (mem == nullptr) { out[oi] = d; continue; }
                float m = fmaf(leak, mem[oi], d);
                float mth = m / thr - 1.0f;
                float s = (mth > 0.0f) ? 1.0f : 0.0f;
                mem[oi] = m - thr * s;
                if (POOL) s_tile[i * TW + j] = s;
                else out[oi] = mask ? s * __ldg(mask + oi) : s;
            }
        }
        if (POOL && mem != nullptr) {
            constexpr int HOP = HO / 2, WOP = WO / 2;
#pragma unroll
            for (int i2 = 0; i2 < TH / 2; ++i2)
#pragma unroll
                for (int j2 = 0; j2 < TW / 2; ++j2) {
                    float sum = s_tile[(2 * i2) * TW + 2 * j2] +
                                s_tile[(2 * i2) * TW + 2 * j2 + 1] +
                                s_tile[(2 * i2 + 1) * TW + 2 * j2] +
                                s_tile[(2 * i2 + 1) * TW + 2 * j2 + 1];
                    out[(((size_t)b * CO + co_p) * HOP + (oh0 >> 1) + i2) * WOP +
                        (ow0 >> 1) + j2] = 0.25f * sum;
                }
        }
    }
}

// FC accumulate: out[b,j] += sum_k in[b,k] * wfc[j,k].  One warp per output.
__global__ __launch_bounds__(256)
void fc_acc(const float* __restrict__ in, const float* __restrict__ wfc,
            float* __restrict__ out) {
    int gw = (blockIdx.x * blockDim.x + threadIdx.x) >> 5;
    int lane = threadIdx.x & 31;
    if (gw >= B * 10) return;
    int b = gw / 10, j = gw % 10;
    const float* x = in + (size_t)b * 2048;
    const float* w = wfc + (size_t)j * 2048;
    float s = 0.f;
    for (int k = lane; k < 2048; k += 32) s = fmaf(x[k], w[k], s);
#pragma unroll
    for (int o = 16; o; o >>= 1) s += __shfl_down_sync(0xffffffffu, s, o);
    if (lane == 0) out[b * 10 + j] += s;
}

// -------------------------- host-side orchestration ------------------------

extern "C" void kernel_launch(void* const* d_in, const int* in_sizes, int n_in,
                              void* d_out, int out_size) {
    const float* x      = (const float*)d_in[0];
    const float* w_pre0 = (const float*)d_in[1];
    const float* w_pre1 = (const float*)d_in[2];
    const float* w_pre2 = (const float*)d_in[3];
    const float* w1a    = (const float*)d_in[4];
    const float* w1b    = (const float*)d_in[5];
    const float* w2a    = (const float*)d_in[6];
    const float* w2b    = (const float*)d_in[7];
    const float* w2i    = (const float*)d_in[8];
    const float* w3a    = (const float*)d_in[9];
    const float* w3b    = (const float*)d_in[10];
    const float* w3i    = (const float*)d_in[11];
    const float* w4a    = (const float*)d_in[12];
    const float* w4b    = (const float*)d_in[13];
    const float* w4i    = (const float*)d_in[14];
    const float* w_fc   = (const float*)d_in[15];
    const float* thr    = (const float*)d_in[16];
    const float* leak   = (const float*)d_in[17];
    const float* mask2  = (const float*)d_in[18];
    const float* mask5  = (const float*)d_in[19];
    const float* mask9  = (const float*)d_in[20];
    const float* mask11 = (const float*)d_in[21];
    const float* mask13 = (const float*)d_in[22];
    const float* mask15 = (const float*)d_in[23];

    float *pm, *pA, *pB, *pC, *pD;
    cudaGetSymbolAddress((void**)&pm, g_mem);
    cudaGetSymbolAddress((void**)&pA, g_A);
    cudaGetSymbolAddress((void**)&pB, g_B);
    cudaGetSymbolAddress((void**)&pC, g_C);
    cudaGetSymbolAddress((void**)&pD, g_D);

    float* m0  = pm + OFF_M0;
    float* m1  = pm + OFF_M1;
    float* m2  = pm + OFF_M2;
    float* m3  = pm + OFF_M3;
    float* m4  = pm + OFF_M4;
    float* m5  = pm + OFF_M5;
    float* m6  = pm + OFF_M6;
    float* m7  = pm + OFF_M7;
    float* m8  = pm + OFF_M8;
    float* m9  = pm + OFF_M9;
    float* m10 = pm + OFF_M10;

    zero_kernel<<<(MEM_TOTAL + 255) / 256, 256>>>(pm, (int)MEM_TOTAL);
    zero_kernel<<<2, 256>>>((float*)d_out, out_size);

    // hoisted: delta0 = conv(x, w_pre0), constant across timesteps
    conv_fused<32, 3, 64, 1, 3, 4, 4, 4, 1, 256, 0, 0, 1><<<512, 256>>>(
        x, w_pre0, nullptr, nullptr, nullptr, nullptr, nullptr, pD, thr, leak, 0);

    for (int t = 0; t < TSTEPS; ++t) {
        // layer 0: elementwise LIF on precomputed delta (float4)
        lif0_kernel<<<2048, 256>>>((const float4*)pD, (float4*)m0,
                                   (const float4*)mask2, (float4*)pA, thr + 0, leak + 0);

        // pre-process convs (32x32, 64ch), CO_PT=2; pre2 fuses the avgpool
        conv_fused<32, 64, 64, 1, 4, 4, 4, 8, 1, 256, 0, 0, 2><<<256, 256>>>(
            pA, w_pre1, nullptr, mask5, nullptr, nullptr, m1, pB, thr, leak, 1);
        conv_fused<32, 64, 64, 1, 4, 4, 4, 8, 1, 256, 0, 1, 2><<<256, 256>>>(
            pB, w_pre2, nullptr, nullptr, nullptr, nullptr, m2, pC, thr, leak, 2);

        // layer1 (identity shortcut), 16x16x64: CO_PT=2 with NT=256 preserved
        conv_fused<16, 64, 64, 1, 8, 2, 4, 16, 1, 256, 0, 0, 2><<<128, 256>>>(
            pC, w1a, nullptr, mask9, nullptr, nullptr, m3, pA, thr, leak, 3);
        conv_fused<16, 64, 64, 1, 8, 2, 4, 16, 1, 256, 0, 0, 2><<<128, 256>>>(
            pA, w1b, pC, nullptr, nullptr, nullptr, m4, pB, thr, leak, 4);

        // layer2: 16x16x64 -> 8x8x128 (fused 1x1-s2 shortcut in conv-b)
        conv_fused<16, 64, 128, 2, 4, 2, 4, 16, 2, 256, 0, 0, 1><<<128, 256>>>(
            pB, w2a, nullptr, mask11, nullptr, nullptr, m5, pC, thr, leak, 5);
        conv_fused<8, 128, 128, 1, 8, 4, 4, 16, 2, 128, 64, 0, 1><<<128, 128>>>(
            pC, w2b, nullptr, nullptr, pB, w2i, m6, pA, thr, leak, 6);

        // layer3: 8x8x128 -> 4x4x256
        conv_fused<8, 128, 256, 2, 8, 2, 2, 16, 2, 128, 0, 0, 1><<<256, 128>>>(
            pA, w3a, nullptr, mask13, nullptr, nullptr, m7, pB, thr, leak, 7);
        conv_fused<4, 256, 256, 1, 8, 2, 4, 32, 2, 128, 128, 0, 1><<<128, 128>>>(
            pB, w3b, nullptr, nullptr, pA, w3i, m8, pC, thr, leak, 8);

        // layer4: 4x4x256 -> 2x2x512
        conv_fused<4, 256, 512, 2, 8, 2, 2, 32, 4, 128, 0, 0, 1><<<128, 128>>>(
            pC, w4a, nullptr, mask15, nullptr, nullptr, m9, pB, thr, leak, 9);
        conv_fused<2, 512, 512, 1, 16, 2, 2, 32, 4, 128, 256, 0, 1><<<128, 128>>>(
            pB, w4b, nullptr, nullptr, pC, w4i, m10, pA, thr, leak, 10);

        // classifier accumulation
        fc_acc<<<40, 256>>>(pA, w_fc, (float*)d_out);
    }
}

// round 17
// speedup vs baseline: 1.0351x; 1.0260x over previous
#include <cuda_runtime.h>
#include <cuda_pipeline.h>

// ---------------------------------------------------------------------------
// SNN ResNet forward, 8 timesteps, B=32. fp32 smem-tiled convs with cp.async
// double buffering, odd-stride weight smem (conflict-free), CO_PT input-load
// reuse on pre convs. Deep layers retiled for >=2 blocks/SM (grid 256).
// Fused LIF / masks / residuals / 1x1-s2 shortcuts / avgpool; layer-0 hoisted.
// ---------------------------------------------------------------------------

#define B 32
#define TSTEPS 8

#define OFF_M0  0u
#define OFF_M1  2097152u
#define OFF_M2  4194304u
#define OFF_M3  6291456u
#define OFF_M4  6815744u
#define OFF_M5  7340032u
#define OFF_M6  7602176u
#define OFF_M7  7864320u
#define OFF_M8  7995392u
#define OFF_M9  8126464u
#define OFF_M10 8192000u
#define MEM_TOTAL 8257536u

__device__ float g_mem[MEM_TOTAL];
__device__ float g_A[2097152];
__device__ float g_B[2097152];
__device__ float g_C[2097152];
__device__ float g_D[2097152];   // precomputed conv(x, w_pre0)

__global__ void zero_kernel(float* __restrict__ p, int n) {
    int i = blockIdx.x * blockDim.x + threadIdx.x;
    if (i < n) p[i] = 0.0f;
}

// elementwise LIF for layer 0, float4-vectorized (delta precomputed)
__global__ __launch_bounds__(256)
void lif0_kernel(const float4* __restrict__ delta, float4* __restrict__ mem,
                 const float4* __restrict__ mask, float4* __restrict__ out,
                 const float* __restrict__ thr_a, const float* __restrict__ leak_a) {
    int i = blockIdx.x * blockDim.x + threadIdx.x;
    float thr = __ldg(thr_a), leak = __ldg(leak_a);
    float4 d = __ldg(delta + i);
    float4 mm = mem[i];
    float4 mk = __ldg(mask + i);
    float4 o, nm;
    { float m = fmaf(leak, mm.x, d.x); float s = (m / thr > 1.0f) ? 1.0f : 0.0f;
      nm.x = m - thr * s; o.x = s * mk.x; }
    { float m = fmaf(leak, mm.y, d.y); float s = (m / thr > 1.0f) ? 1.0f : 0.0f;
      nm.y = m - thr * s; o.y = s * mk.y; }
    { float m = fmaf(leak, mm.z, d.z); float s = (m / thr > 1.0f) ? 1.0f : 0.0f;
      nm.z = m - thr * s; o.z = s * mk.z; }
    { float m = fmaf(leak, mm.w, d.w); float s = (m / thr > 1.0f) ? 1.0f : 0.0f;
      nm.w = m - thr * s; o.w = s * mk.w; }
    mem[i] = nm;
    out[i] = o;
}

// ---------------------------------------------------------------------------
// Fused 3x3 conv (pad=1) + (residual | fused 1x1-s2 shortcut) + LIF + mask
// (+ optional fused 2x2 avgpool). Double-buffered cp.async chunk staging.
// Each thread computes CO_PT consecutive output channels (input-load reuse).
// mem == nullptr  =>  raw conv output (no LIF), used for hoisted layer 0.
// ---------------------------------------------------------------------------
template<int H, int CI, int CO, int STRIDE, int CIC, int TH, int TW,
         int CO_T, int B_T, int NT, int SC_CI, int POOL, int CO_PT>
__global__ __launch_bounds__(NT)
void conv_fused(const float* __restrict__ in, const float* __restrict__ wgt,
                const float* __restrict__ res, const float* __restrict__ mask,
                const float* __restrict__ sc_in, const float* __restrict__ sc_w,
                float* __restrict__ mem, float* __restrict__ out,
                const float* __restrict__ thr_a, const float* __restrict__ leak_a,
                int lidx) {
    constexpr int HO = H / STRIDE;
    constexpr int WO = HO;
    constexpr int TILESH = HO / TH;
    constexpr int TILESW = WO / TW;
    constexpr int TILES = TILESH * TILESW;
    constexpr int CO_G = CO_T / CO_PT;
    static_assert(TILES * CO_G * B_T == NT, "thread count mismatch");
    static_assert((TW * STRIDE) % 4 == 0 || TILESW == 1, "LDS.128 alignment");
    constexpr int RH = (TH - 1) * STRIDE + 3;
    constexpr int RW = (TW - 1) * STRIDE + 3;
    constexpr int NV4 = (RW + 3) / 4;
    constexpr int SWMIN = (H + 2 > NV4 * 4) ? (H + 2) : (NV4 * 4);
    constexpr int SW = ((SWMIN + 3) / 4) * 4;   // smem row stride (interior col 1)
    constexpr int HI2 = H + 2;
    constexpr int IN_CH = HI2 * SW;
    constexpr int IN_IMG = CIC * IN_CH;
    constexpr int IN_TOT = B_T * IN_IMG;
    constexpr int W_CO = CIC * 9;
    constexpr int W_STRIDE = W_CO + 1;          // ODD stride -> conflict-free
    constexpr int W_TOT = CO_T * W_STRIDE;
    constexpr int CHUNKS = CI / CIC;
    constexpr int THW = TH * TW;

    __shared__ alignas(16) float s_in[2][IN_TOT];
    __shared__ alignas(16) float s_w[2][W_TOT];

    const int tid = threadIdx.x;
    const int tile = tid % TILES;
    const int cs   = (tid / TILES) % CO_G;
    const int b_l  = tid / (TILES * CO_G);
    const int co_g = blockIdx.x % (CO / CO_T);
    const int b_g  = blockIdx.x / (CO / CO_T);
    const int b  = b_g * B_T + b_l;
    const int co = co_g * CO_T + cs * CO_PT;
    const int oh0 = (tile / TILESW) * TH;
    const int ow0 = (tile % TILESW) * TW;

    // zero both input buffers once: halo / padding stays zero for all chunks
    {
        const float4 z4 = make_float4(0.f, 0.f, 0.f, 0.f);
        for (int i = tid * 4; i < IN_TOT; i += NT * 4) {
            *reinterpret_cast<float4*>(&s_in[0][i]) = z4;
            *reinterpret_cast<float4*>(&s_in[1][i]) = z4;
        }
    }
    __syncthreads();

    auto stage = [&](int buf, int cc) {
        constexpr int NE = B_T * CIC * H * H;
        for (int e = tid; e < NE; e += NT) {
            const int wq = e % H;
            int r = e / H;
            const int h = r % H; r /= H;
            const int ci = r % CIC;
            const int bl = r / CIC;
            const float* src = in + (((size_t)(b_g * B_T + bl) * CI + cc * CIC + ci) * H + h) * H + wq;
            __pipeline_memcpy_async(&s_in[buf][bl * IN_IMG + ci * IN_CH + (h + 1) * SW + 1 + wq],
                                    src, 4);
        }
        for (int e = tid; e < CO_T * W_CO; e += NT) {
            const int rem = e % W_CO;
            const int col = e / W_CO;
            const float* src = wgt + ((size_t)(co_g * CO_T + col) * CI + cc * CIC) * 9 + rem;
            __pipeline_memcpy_async(&s_w[buf][col * W_STRIDE + rem], src, 4);
        }
    };

    float acc[CO_PT][THW];
#pragma unroll
    for (int p = 0; p < CO_PT; ++p)
#pragma unroll
        for (int i = 0; i < THW; ++i) acc[p][i] = 0.0f;

    stage(0, 0);
    __pipeline_commit();

    for (int cc = 0; cc < CHUNKS; ++cc) {
        const int cur = cc & 1;
        if (cc + 1 < CHUNKS) {
            stage(cur ^ 1, cc + 1);
            __pipeline_commit();
            __pipeline_wait_prior(1);
        } else {
            __pipeline_wait_prior(0);
        }
        __syncthreads();

        const float* sin_b = &s_in[cur][b_l * IN_IMG + (oh0 * STRIDE) * SW + ow0 * STRIDE];
        const float* sw_c  = &s_w[cur][(cs * CO_PT) * W_STRIDE];
        for (int ci = 0; ci < CIC; ++ci) {
            float w9[CO_PT][9];
#pragma unroll
            for (int p = 0; p < CO_PT; ++p)
#pragma unroll
                for (int k = 0; k < 9; ++k) w9[p][k] = sw_c[p * W_STRIDE + ci * 9 + k];
            const float* sp = sin_b + ci * IN_CH;
#pragma unroll
            for (int r = 0; r < RH; ++r) {
                float v[NV4 * 4];
#pragma unroll
                for (int q = 0; q < NV4; ++q)
                    *reinterpret_cast<float4*>(v + 4 * q) =
                        *reinterpret_cast<const float4*>(sp + r * SW + 4 * q);
#pragma unroll
                for (int kh = 0; kh < 3; ++kh) {
                    if (r - kh >= 0 && (r - kh) % STRIDE == 0 && (r - kh) / STRIDE < TH) {
                        const int ii = (r - kh) / STRIDE;
#pragma unroll
                        for (int kw = 0; kw < 3; ++kw)
#pragma unroll
                            for (int j = 0; j < TW; ++j)
#pragma unroll
                                for (int p = 0; p < CO_PT; ++p)
                                    acc[p][ii * TW + j] = fmaf(w9[p][kh * 3 + kw],
                                                               v[j * STRIDE + kw],
                                                               acc[p][ii * TW + j]);
                    }
                }
            }
        }
        __syncthreads();
    }

    // fused 1x1-s2 shortcut conv (input loads shared across CO_PT)
    float rsum[CO_PT][THW];
    if (SC_CI > 0) {
#pragma unroll
        for (int p = 0; p < CO_PT; ++p)
#pragma unroll
            for (int i = 0; i < THW; ++i) rsum[p][i] = 0.0f;
        for (int ci = 0; ci < SC_CI; ++ci) {
            float wv[CO_PT];
#pragma unroll
            for (int p = 0; p < CO_PT; ++p)
                wv[p] = __ldg(sc_w + (size_t)(co + p) * SC_CI + ci);
            const float* ip = sc_in + ((size_t)b * SC_CI + ci) * (4 * HO * WO);
#pragma unroll
            for (int i = 0; i < TH; ++i)
#pragma unroll
                for (int j = 0; j < TW; ++j) {
                    float iv = __ldg(ip + (2 * (oh0 + i)) * (2 * WO) + 2 * (ow0 + j));
#pragma unroll
                    for (int p = 0; p < CO_PT; ++p)
                        rsum[p][i * TW + j] = fmaf(wv[p], iv, rsum[p][i * TW + j]);
                }
        }
    }

    const float thr  = __ldg(thr_a + lidx);
    const float leak = __ldg(leak_a + lidx);

#pragma unroll
    for (int p = 0; p < CO_PT; ++p) {
        const int co_p = co + p;
        float s_tile[THW];
#pragma unroll
        for (int i = 0; i < TH; ++i) {
#pragma unroll
            for (int j = 0; j < TW; ++j) {
                size_t oi = (((size_t)b * CO + co_p) * HO + oh0 + i) * WO + ow0 + j;
                float d = acc[p][i * TW + j];
                if (SC_CI > 0) d += rsum[p][i * TW + j];
                else if (res) d += __ldg(res + oi);
                if (mem == nullptr) { out[oi] = d; continue; }
                float m = fmaf(leak, mem[oi], d);
                float mth = m / thr - 1.0f;
                float s = (mth > 0.0f) ? 1.0f : 0.0f;
                mem[oi] = m - thr * s;
                if (POOL) s_tile[i * TW + j] = s;
                else out[oi] = mask ? s * __ldg(mask + oi) : s;
            }
        }
        if (POOL && mem != nullptr) {
            constexpr int HOP = HO / 2, WOP = WO / 2;
#pragma unroll
            for (int i2 = 0; i2 < TH / 2; ++i2)
#pragma unroll
                for (int j2 = 0; j2 < TW / 2; ++j2) {
                    float sum = s_tile[(2 * i2) * TW + 2 * j2] +
                                s_tile[(2 * i2) * TW + 2 * j2 + 1] +
                                s_tile[(2 * i2 + 1) * TW + 2 * j2] +
                                s_tile[(2 * i2 + 1) * TW + 2 * j2 + 1];
                    out[(((size_t)b * CO + co_p) * HOP + (oh0 >> 1) + i2) * WOP +
                        (ow0 >> 1) + j2] = 0.25f * sum;
                }
        }
    }
}

// FC accumulate: out[b,j] += sum_k in[b,k] * wfc[j,k].  One warp per output.
__global__ __launch_bounds__(256)
void fc_acc(const float* __restrict__ in, const float* __restrict__ wfc,
            float* __restrict__ out) {
    int gw = (blockIdx.x * blockDim.x + threadIdx.x) >> 5;
    int lane = threadIdx.x & 31;
    if (gw >= B * 10) return;
    int b = gw / 10, j = gw % 10;
    const float* x = in + (size_t)b * 2048;
    const float* w = wfc + (size_t)j * 2048;
    float s = 0.f;
    for (int k = lane; k < 2048; k += 32) s = fmaf(x[k], w[k], s);
#pragma unroll
    for (int o = 16; o; o >>= 1) s += __shfl_down_sync(0xffffffffu, s, o);
    if (lane == 0) out[b * 10 + j] += s;
}

// -------------------------- host-side orchestration ------------------------

extern "C" void kernel_launch(void* const* d_in, const int* in_sizes, int n_in,
                              void* d_out, int out_size) {
    const float* x      = (const float*)d_in[0];
    const float* w_pre0 = (const float*)d_in[1];
    const float* w_pre1 = (const float*)d_in[2];
    const float* w_pre2 = (const float*)d_in[3];
    const float* w1a    = (const float*)d_in[4];
    const float* w1b    = (const float*)d_in[5];
    const float* w2a    = (const float*)d_in[6];
    const float* w2b    = (const float*)d_in[7];
    const float* w2i    = (const float*)d_in[8];
    const float* w3a    = (const float*)d_in[9];
    const float* w3b    = (const float*)d_in[10];
    const float* w3i    = (const float*)d_in[11];
    const float* w4a    = (const float*)d_in[12];
    const float* w4b    = (const float*)d_in[13];
    const float* w4i    = (const float*)d_in[14];
    const float* w_fc   = (const float*)d_in[15];
    const float* thr    = (const float*)d_in[16];
    const float* leak   = (const float*)d_in[17];
    const float* mask2  = (const float*)d_in[18];
    const float* mask5  = (const float*)d_in[19];
    const float* mask9  = (const float*)d_in[20];
    const float* mask11 = (const float*)d_in[21];
    const float* mask13 = (const float*)d_in[22];
    const float* mask15 = (const float*)d_in[23];

    float *pm, *pA, *pB, *pC, *pD;
    cudaGetSymbolAddress((void**)&pm, g_mem);
    cudaGetSymbolAddress((void**)&pA, g_A);
    cudaGetSymbolAddress((void**)&pB, g_B);
    cudaGetSymbolAddress((void**)&pC, g_C);
    cudaGetSymbolAddress((void**)&pD, g_D);

    float* m0  = pm + OFF_M0;
    float* m1  = pm + OFF_M1;
    float* m2  = pm + OFF_M2;
    float* m3  = pm + OFF_M3;
    float* m4  = pm + OFF_M4;
    float* m5  = pm + OFF_M5;
    float* m6  = pm + OFF_M6;
    float* m7  = pm + OFF_M7;
    float* m8  = pm + OFF_M8;
    float* m9  = pm + OFF_M9;
    float* m10 = pm + OFF_M10;

    zero_kernel<<<(MEM_TOTAL + 255) / 256, 256>>>(pm, (int)MEM_TOTAL);
    zero_kernel<<<2, 256>>>((float*)d_out, out_size);

    // hoisted: delta0 = conv(x, w_pre0), constant across timesteps
    conv_fused<32, 3, 64, 1, 3, 4, 4, 4, 1, 256, 0, 0, 1><<<512, 256>>>(
        x, w_pre0, nullptr, nullptr, nullptr, nullptr, nullptr, pD, thr, leak, 0);

    for (int t = 0; t < TSTEPS; ++t) {
        // layer 0: elementwise LIF on precomputed delta (float4)
        lif0_kernel<<<2048, 256>>>((const float4*)pD, (float4*)m0,
                                   (const float4*)mask2, (float4*)pA, thr + 0, leak + 0);

        // pre-process convs (32x32, 64ch), CO_PT=2; pre2 fuses the avgpool
        conv_fused<32, 64, 64, 1, 4, 4, 4, 8, 1, 256, 0, 0, 2><<<256, 256>>>(
            pA, w_pre1, nullptr, mask5, nullptr, nullptr, m1, pB, thr, leak, 1);
        conv_fused<32, 64, 64, 1, 4, 4, 4, 8, 1, 256, 0, 1, 2><<<256, 256>>>(
            pB, w_pre2, nullptr, nullptr, nullptr, nullptr, m2, pC, thr, leak, 2);

        // layer1 (identity shortcut), 16x16x64 — R14 config
        conv_fused<16, 64, 64, 1, 8, 4, 4, 16, 1, 256, 0, 0, 1><<<128, 256>>>(
            pC, w1a, nullptr, mask9, nullptr, nullptr, m3, pA, thr, leak, 3);
        conv_fused<16, 64, 64, 1, 8, 4, 4, 16, 1, 256, 0, 0, 1><<<128, 256>>>(
            pA, w1b, pC, nullptr, nullptr, nullptr, m4, pB, thr, leak, 4);

        // layer2: 16x16x64 -> 8x8x128 (fused 1x1-s2 shortcut in conv-b)
        conv_fused<16, 64, 128, 2, 4, 2, 4, 16, 2, 256, 0, 0, 1><<<128, 256>>>(
            pB, w2a, nullptr, mask11, nullptr, nullptr, m5, pC, thr, leak, 5);
        conv_fused<8, 128, 128, 1, 8, 2, 4, 8, 2, 128, 64, 0, 1><<<256, 128>>>(
            pC, w2b, nullptr, nullptr, pB, w2i, m6, pA, thr, leak, 6);

        // layer3: 8x8x128 -> 4x4x256
        conv_fused<8, 128, 256, 2, 8, 2, 2, 16, 2, 128, 0, 0, 1><<<256, 128>>>(
            pA, w3a, nullptr, mask13, nullptr, nullptr, m7, pB, thr, leak, 7);
        conv_fused<4, 256, 256, 1, 8, 1, 4, 16, 2, 128, 128, 0, 1><<<256, 128>>>(
            pB, w3b, nullptr, nullptr, pA, w3i, m8, pC, thr, leak, 8);

        // layer4: 4x4x256 -> 2x2x512
        conv_fused<4, 256, 512, 2, 8, 1, 2, 16, 4, 128, 0, 0, 1><<<256, 128>>>(
            pC, w4a, nullptr, mask15, nullptr, nullptr, m9, pB, thr, leak, 9);
        conv_fused<2, 512, 512, 1, 16, 1, 2, 16, 4, 128, 256, 0, 1><<<256, 128>>>(
            pB, w4b, nullptr, nullptr, pC, w4i, m10, pA, thr, leak, 10);

        // classifier accumulation
        fc_acc<<<40, 256>>>(pA, w_fc, (float*)d_out);
    }
}